// round 11
// baseline (speedup 1.0000x reference)
#include <cuda_runtime.h>

// Sineconv: out[b,l,f] = sum_{w=0}^{64} x[b, l + 2f + ((f+w)>>5)] * sines[f, l+w]
//                        + x[b, l+32] * res_kernel[f]
// sines[f,s] = amplitude[f] * sin( ((frequency[f]*19000)*2pi) * sine_range[s] + phases[f]*2pi )
//
// x factor is piecewise-constant in w over 3 ranges -> each output needs
// 3 contiguous range-sums of sines (local fp32 prefix scan) + residual.
//
// R11: TILE_L=128 (1.5x halo, 75% of R9's sine work) *and* R9's warp count:
// FG=4, 2 warps per sine row (96 samples each, 3/lane) -> 1024 CTAs, 8192
// warps, single wave at 7 CTAs/SM. Half-0 warp stores global-exclusive
// prefixes + row total T; half-1 stores half-local prefixes; epilogue adds
// T predicated on idx>=96 (no fixup pass, single barrier).

#define S_TOTAL 16384
#define L_OUT   16320
#define F_N     32
#define B_N     4
#define TILE_L  128
#define FG      4               // features per block
#define NW      192             // window samples; prefix indices 0..192
#define NPP     196             // Psh row stride
#define XW      196             // xsh row stride (only 0..191 used)

// Accurate sinf via fp32 FMA Cody-Waite (exact internal products).
// |arg| <= ~1e5 here: total reduction error ~6e-8 rad.
__device__ __forceinline__ float acc_sinf(float a) {
    float kf = rintf(a * 0.63661977236758134f);          // 2/pi
    float r  = fmaf(-kf, 1.57079637050628662e+0f, a);    // c1 = float(pi/2)
    r        = fmaf(-kf, -4.37113900018624283e-8f, r);   // c2 = float(pi/2 - c1)
    int   q  = (int)kf;
    float r2 = r * r;
    float sp = fmaf(r2, fmaf(r2, fmaf(r2, -1.9841269841e-4f, 8.3333333333e-3f),
                             -1.6666666667e-1f), 1.0f);
    float s  = r * sp;
    float c  = fmaf(r2, fmaf(r2, fmaf(r2, fmaf(r2, 2.4801587302e-5f, -1.3888888889e-3f),
                             4.1666666667e-2f), -5.0e-1f), 1.0f);
    float v = (q & 1) ? c : s;
    return (q & 2) ? -v : v;
}

__global__ __launch_bounds__(256, 7) void sineconv_kernel(
    const float* __restrict__ x,          // (B, S, 1)
    const float* __restrict__ sr,         // (S,)
    const float* __restrict__ phases,     // (32,)
    const float* __restrict__ amplitude,  // (32,)
    const float* __restrict__ frequency,  // (32,)
    const float* __restrict__ res_kernel, // (32,)
    float* __restrict__ out)              // (B, L, F)
{
    __shared__ __align__(16) float Psh[FG][NPP];  // prefix: [0,96) global-excl, [96,192] half-local
    __shared__ __align__(16) float xsh[B_N][XW];
    __shared__ float Tsh[FG];                     // total of samples [0,96) per row

    const int tid  = threadIdx.x;
    const int lane = tid & 31;
    const int warp = tid >> 5;
    const int s0   = blockIdx.x * TILE_L;
    const int fg0  = blockIdx.y * FG;

    // ---- stage x: 192 floats per batch (max index read: xb+2 = 191).
    if (tid < 192) {
        int b = tid / 48;
        int j = tid - b * 48;             // float4 index within batch row
        float4 v = make_float4(0.f, 0.f, 0.f, 0.f);
        if (s0 + 4 * j + 3 < S_TOTAL)     // float4 fully in or fully out
            v = ((const float4*)(x + b * S_TOTAL + s0))[j];
        *((float4*)&xsh[b][4 * j]) = v;
    }

    // ---- sines + scan: warp pair (2r, 2r+1) owns row r; 96 samples/warp ----
    {
        const float TWO_PI = 6.28318530717958647692f;
        const int rl = warp >> 1;         // local row 0..3
        const int h  = warp & 1;          // half: 0 -> [0,96), 1 -> [96,192)
        const int f  = fg0 + rl;
        // Replicate reference fp32 rounding: ((freq*19000)*2pi)*sr + ph
        float w2  = __fmul_rn(__fmul_rn(frequency[f], 19000.0f), TWO_PI);
        float ph  = __fmul_rn(phases[f], TWO_PI);
        float amp = amplitude[f];

        const int j0 = 96 * h + 3 * lane; // lane owns samples j0..j0+2
        float v0 = 0.f, v1 = 0.f, v2 = 0.f;
        if (s0 + j0     < S_TOTAL) v0 = __fmul_rn(amp, acc_sinf(__fadd_rn(__fmul_rn(w2, sr[s0 + j0    ]), ph)));
        if (s0 + j0 + 1 < S_TOTAL) v1 = __fmul_rn(amp, acc_sinf(__fadd_rn(__fmul_rn(w2, sr[s0 + j0 + 1]), ph)));
        if (s0 + j0 + 2 < S_TOTAL) v2 = __fmul_rn(amp, acc_sinf(__fadd_rn(__fmul_rn(w2, sr[s0 + j0 + 2]), ph)));
        float loc0 = v0;
        float loc1 = loc0 + v1;
        float run  = loc1 + v2;
        // exclusive scan of lane totals within the warp (local to this half)
        float t = run;
#pragma unroll
        for (int off = 1; off < 32; off <<= 1) {
            float n = __shfl_up_sync(0xFFFFFFFFu, t, off);
            if (lane >= off) t += n;
        }
        float excl = t - run;             // half-local exclusive prefix before j0
        Psh[rl][j0]     = excl;
        Psh[rl][j0 + 1] = excl + loc0;
        Psh[rl][j0 + 2] = excl + loc1;
        if (lane == 31) {
            if (h == 0) Tsh[rl] = excl + run;        // total of samples [0,96)
            else        Psh[rl][NW] = excl + run;    // half-local prefix at idx 192
        }
    }
    __syncthreads();

    // ---- epilogue: fl = tid&3, i0 = tid>>2 (0..63), 2 l-passes x 4 batches ----
    const int fl = tid & 3;
    const int f  = fg0 + fl;
    const int i0 = tid >> 2;
    const float rk = res_kernel[f];
    const float T  = Tsh[fl];
    const int i32 = 32 - f;
    const int i64 = 64 - f;

#pragma unroll
    for (int p = 0; p < 2; p++) {
        int i = i0 + p * 64;             // local l index, 0..127
        int l = s0 + i;
        int ja = i + i32, jb = i + i64, jc = i + 65;
        float p0 = Psh[fl][i]  + ((i  >= 96) ? T : 0.0f);
        float pa = Psh[fl][ja] + ((ja >= 96) ? T : 0.0f);
        float pb = Psh[fl][jb] + ((jb >= 96) ? T : 0.0f);
        float p3 = Psh[fl][jc] + ((jc >= 96) ? T : 0.0f);
        float A0 = pa - p0;              // sum sines[f, l .. l+31-f]
        float A1 = pb - pa;              // sum sines[f, l+32-f .. l+63-f]
        float A2 = p3 - pb;              // sum sines[f, l+64-f .. l+64]
        int xb = i + 2 * f;
        if (l < L_OUT) {
#pragma unroll
            for (int b = 0; b < B_N; b++) {
                float r = fmaf(xsh[b][xb],     A0,
                          fmaf(xsh[b][xb + 1], A1,
                          fmaf(xsh[b][xb + 2], A2,
                               xsh[b][i + 32] * rk)));
                out[(b * L_OUT + l) * F_N + f] = r;
            }
        }
    }
}

extern "C" void kernel_launch(void* const* d_in, const int* in_sizes, int n_in,
                              void* d_out, int out_size) {
    const float* x    = (const float*)d_in[0];
    const float* sr   = (const float*)d_in[1];
    const float* ph   = (const float*)d_in[2];
    const float* amp  = (const float*)d_in[3];
    const float* freq = (const float*)d_in[4];
    const float* rk   = (const float*)d_in[5];
    float* out = (float*)d_out;

    dim3 grid((L_OUT + TILE_L - 1) / TILE_L, F_N / FG);
    sineconv_kernel<<<grid, 256>>>(x, sr, ph, amp, freq, rk, out);
}

// round 12
// speedup vs baseline: 1.2657x; 1.2657x over previous
#include <cuda_runtime.h>

// Sineconv: out[b,l,f] = sum_{w=0}^{64} x[b, l + 2f + ((f+w)>>5)] * sines[f, l+w]
//                        + x[b, l+32] * res_kernel[f]
// sines[f,s] = amplitude[f] * sin( ((frequency[f]*19000)*2pi) * sine_range[s] + phases[f]*2pi )
//
// x factor is piecewise-constant in w over 3 ranges -> each output needs
// 3 contiguous range-sums of sines (local fp32 prefix scan) + residual.
//
// R12: TILE_L=128 work saving (1.5x halo, 786K sines) at R9's warp count,
// with clean vector loads (R11's stride-3 scalar LDGs caused its regression).
// 512-thread CTAs, FG=8, 512 CTAs, 16 warps: warp pair per row, split
// [0,128) (R9's exact 4/lane LDG.128 scan) / [128,192) (2/lane LDG.64);
// h1 warps also stage x. Prefix stitch via Tsh[row], predicated +T (only
// indices >= 128; p0 never needs it). Single wave at 4 CTAs/SM (cap 528).

#define S_TOTAL 16384
#define L_OUT   16320
#define F_N     32
#define B_N     4
#define TILE_L  128
#define FG      8               // features per block
#define NW      192             // window samples; prefix indices 0..192
#define NPP     196             // Psh row stride (784B, 16B-aligned rows)
#define XW      196             // xsh row stride (only 0..191 used)

// Accurate sinf via fp32 FMA Cody-Waite (exact internal products).
// |arg| <= ~1e5 here: total reduction error ~6e-8 rad.
__device__ __forceinline__ float acc_sinf(float a) {
    float kf = rintf(a * 0.63661977236758134f);          // 2/pi
    float r  = fmaf(-kf, 1.57079637050628662e+0f, a);    // c1 = float(pi/2)
    r        = fmaf(-kf, -4.37113900018624283e-8f, r);   // c2 = float(pi/2 - c1)
    int   q  = (int)kf;
    float r2 = r * r;
    float sp = fmaf(r2, fmaf(r2, fmaf(r2, -1.9841269841e-4f, 8.3333333333e-3f),
                             -1.6666666667e-1f), 1.0f);
    float s  = r * sp;
    float c  = fmaf(r2, fmaf(r2, fmaf(r2, fmaf(r2, 2.4801587302e-5f, -1.3888888889e-3f),
                             4.1666666667e-2f), -5.0e-1f), 1.0f);
    float v = (q & 1) ? c : s;
    return (q & 2) ? -v : v;
}

__global__ __launch_bounds__(512, 4) void sineconv_kernel(
    const float* __restrict__ x,          // (B, S, 1)
    const float* __restrict__ sr,         // (S,)
    const float* __restrict__ phases,     // (32,)
    const float* __restrict__ amplitude,  // (32,)
    const float* __restrict__ frequency,  // (32,)
    const float* __restrict__ res_kernel, // (32,)
    float* __restrict__ out)              // (B, L, F)
{
    __shared__ __align__(16) float Psh[FG][NPP];  // [0,128): global-excl; [128,192]: half-local
    __shared__ __align__(16) float xsh[B_N][XW];
    __shared__ float Tsh[FG];                     // total of samples [0,128) per row

    const int tid  = threadIdx.x;
    const int lane = tid & 31;
    const int warp = tid >> 5;       // 0..15
    const int rl   = warp >> 1;      // local feature row 0..7
    const int h    = warp & 1;       // half: 0 -> [0,128), 1 -> [128,192)
    const int s0   = blockIdx.x * TILE_L;
    const int fg0  = blockIdx.y * FG;

    {
        const float TWO_PI = 6.28318530717958647692f;
        const int f = fg0 + rl;
        // Replicate reference fp32 rounding: ((freq*19000)*2pi)*sr + ph
        float w2  = __fmul_rn(__fmul_rn(frequency[f], 19000.0f), TWO_PI);
        float ph  = __fmul_rn(phases[f], TWO_PI);
        float amp = amplitude[f];

        if (h == 0) {
            // ---- samples [0,128): 4/lane via one LDG.128 (always in bounds) ----
            float4 sv = ((const float4*)(sr + s0))[lane];
            float v0 = __fmul_rn(amp, acc_sinf(__fadd_rn(__fmul_rn(w2, sv.x), ph)));
            float v1 = __fmul_rn(amp, acc_sinf(__fadd_rn(__fmul_rn(w2, sv.y), ph)));
            float v2 = __fmul_rn(amp, acc_sinf(__fadd_rn(__fmul_rn(w2, sv.z), ph)));
            float v3 = __fmul_rn(amp, acc_sinf(__fadd_rn(__fmul_rn(w2, sv.w), ph)));
            float loc0 = v0;
            float loc1 = loc0 + v1;
            float loc2 = loc1 + v2;
            float run  = loc2 + v3;
            float t = run;
#pragma unroll
            for (int off = 1; off < 32; off <<= 1) {
                float n = __shfl_up_sync(0xFFFFFFFFu, t, off);
                if (lane >= off) t += n;
            }
            float excl = t - run;            // global exclusive prefix before 4*lane
            float4 w4;
            w4.x = excl;
            w4.y = excl + loc0;
            w4.z = excl + loc1;
            w4.w = excl + loc2;
            *((float4*)&Psh[rl][4 * lane]) = w4;
            if (lane == 31) Tsh[rl] = excl + run;    // sum of samples [0,128)
        } else {
            // ---- samples [128,192): 2/lane via one guarded LDG.64; also stage x ----
            const int j0 = 128 + 2 * lane;
            float2 sv = make_float2(0.f, 0.f);
            bool in0 = (s0 + j0     < S_TOTAL);
            bool in1 = (s0 + j0 + 1 < S_TOTAL);
            if (in1) sv = *(const float2*)(sr + s0 + j0);     // float2 fully in
            else if (in0) sv.x = sr[s0 + j0];

            // x stage: 192 float4 among the 256 h1 threads (issued while sr in flight)
            const int idx = rl * 32 + lane;                   // 0..255
            float4 xv = make_float4(0.f, 0.f, 0.f, 0.f);
            int xb_ = 0, xj = 0;
            if (idx < 192) {
                xb_ = idx / 48;
                xj  = idx - xb_ * 48;
                if (s0 + 4 * xj + 3 < S_TOTAL)                // fully in or fully out
                    xv = ((const float4*)(x + xb_ * S_TOTAL + s0))[xj];
            }

            float v0 = in0 ? __fmul_rn(amp, acc_sinf(__fadd_rn(__fmul_rn(w2, sv.x), ph))) : 0.f;
            float v1 = in1 ? __fmul_rn(amp, acc_sinf(__fadd_rn(__fmul_rn(w2, sv.y), ph))) : 0.f;
            float loc0 = v0;
            float run  = loc0 + v1;
            float t = run;
#pragma unroll
            for (int off = 1; off < 32; off <<= 1) {
                float n = __shfl_up_sync(0xFFFFFFFFu, t, off);
                if (lane >= off) t += n;
            }
            float excl = t - run;            // half-local exclusive prefix before j0

            if (idx < 192) *((float4*)&xsh[xb_][4 * xj]) = xv;
            *((float2*)&Psh[rl][j0]) = make_float2(excl, excl + loc0);
            if (lane == 31) Psh[rl][NW] = excl + run;         // half-local, idx 192
        }
    }
    __syncthreads();

    // ---- epilogue: fl = tid&7, i0 = tid>>3 (0..63), 2 l-passes x 4 batches ----
    const int fl = tid & 7;
    const int f  = fg0 + fl;
    const int i0 = tid >> 3;
    const float rk = res_kernel[f];
    const float T  = Tsh[fl];
    const int i32 = 32 - f;
    const int i64 = 64 - f;

#pragma unroll
    for (int p = 0; p < 2; p++) {
        int i = i0 + p * 64;             // local l index, 0..127
        int l = s0 + i;
        int ja = i + i32, jb = i + i64, jc = i + 65;
        float p0 = Psh[fl][i];                                 // i <= 127: never +T
        float pa = Psh[fl][ja] + ((ja >= 128) ? T : 0.0f);
        float pb = Psh[fl][jb] + ((jb >= 128) ? T : 0.0f);
        float p3 = Psh[fl][jc] + ((jc >= 128) ? T : 0.0f);
        float A0 = pa - p0;              // sum sines[f, l .. l+31-f]
        float A1 = pb - pa;              // sum sines[f, l+32-f .. l+63-f]
        float A2 = p3 - pb;              // sum sines[f, l+64-f .. l+64]
        int xb = i + 2 * f;
        if (l < L_OUT) {
#pragma unroll
            for (int b = 0; b < B_N; b++) {
                float r = fmaf(xsh[b][xb],     A0,
                          fmaf(xsh[b][xb + 1], A1,
                          fmaf(xsh[b][xb + 2], A2,
                               xsh[b][i + 32] * rk)));
                out[(b * L_OUT + l) * F_N + f] = r;
            }
        }
    }
}

extern "C" void kernel_launch(void* const* d_in, const int* in_sizes, int n_in,
                              void* d_out, int out_size) {
    const float* x    = (const float*)d_in[0];
    const float* sr   = (const float*)d_in[1];
    const float* ph   = (const float*)d_in[2];
    const float* amp  = (const float*)d_in[3];
    const float* freq = (const float*)d_in[4];
    const float* rk   = (const float*)d_in[5];
    float* out = (float*)d_out;

    dim3 grid((L_OUT + TILE_L - 1) / TILE_L, F_N / FG);
    sineconv_kernel<<<grid, 512>>>(x, sr, ph, amp, freq, rk, out);
}